// round 1
// baseline (speedup 1.0000x reference)
#include <cuda_runtime.h>
#include <cuda_bf16.h>
#include <math.h>

// Problem constants
#define N_TOK 4096
#define D_DIM 1024
#define H_DIM 4096
#define O_DIM 1024
#define E_NUM 8

// GEMM tiling
#define BM 128
#define BN 128
#define BK 8

// ---------------- device scratch (static; no cudaMalloc allowed) ----------------
__device__ float g_h[(size_t)E_NUM * N_TOK * H_DIM];   // 512 MB: hidden activations per (expert,row)
__device__ int   g_sel[N_TOK * 2];
__device__ float g_w[N_TOK * 2];
__device__ int   g_list[E_NUM * N_TOK];
__device__ float g_lw[E_NUM * N_TOK];
__device__ int   g_count[E_NUM];

// ---------------- gate: logits -> relu -> top2 (+jax tie-break) -> weights ----------------
__global__ void gate_kernel(const float* __restrict__ x, const float* __restrict__ Wg) {
    int t = blockIdx.x;
    int tid = threadIdx.x;  // 256 threads
    const float* xr = x + (size_t)t * D_DIM;

    float acc[E_NUM];
#pragma unroll
    for (int e = 0; e < E_NUM; e++) acc[e] = 0.f;

    for (int d = tid; d < D_DIM; d += 256) {
        float xv = xr[d];
        const float4 w0 = *(const float4*)(Wg + (size_t)d * E_NUM);
        const float4 w1 = *(const float4*)(Wg + (size_t)d * E_NUM + 4);
        acc[0] += xv * w0.x; acc[1] += xv * w0.y; acc[2] += xv * w0.z; acc[3] += xv * w0.w;
        acc[4] += xv * w1.x; acc[5] += xv * w1.y; acc[6] += xv * w1.z; acc[7] += xv * w1.w;
    }

    __shared__ float red[E_NUM][256];
#pragma unroll
    for (int e = 0; e < E_NUM; e++) red[e][tid] = acc[e];
    __syncthreads();
    for (int s = 128; s > 0; s >>= 1) {
        if (tid < s) {
#pragma unroll
            for (int e = 0; e < E_NUM; e++) red[e][tid] += red[e][tid + s];
        }
        __syncthreads();
    }

    if (tid == 0) {
        float v[E_NUM];
#pragma unroll
        for (int e = 0; e < E_NUM; e++) v[e] = fmaxf(red[e][0], 0.f);
        // first-occurrence argmax (jax top_k tie-break: ascending index among ties)
        int i1 = 0; float m1 = v[0];
#pragma unroll
        for (int e = 1; e < E_NUM; e++) if (v[e] > m1) { m1 = v[e]; i1 = e; }
        int i2 = -1; float m2 = -1e30f;
#pragma unroll
        for (int e = 0; e < E_NUM; e++) if (e != i1 && v[e] > m2) { m2 = v[e]; i2 = e; }
        // normalized pair weights: softmax denominators cancel
        float eb = __expf(m2 - m1);
        float inv = 1.f / (1.f + eb);
        g_sel[t * 2 + 0] = i1;  g_w[t * 2 + 0] = inv;
        g_sel[t * 2 + 1] = i2;  g_w[t * 2 + 1] = eb * inv;
    }
}

// ---------------- deterministic per-expert list build via block scan ----------------
__global__ void build_lists_kernel() {
    int e = blockIdx.x;          // one block per expert
    int tid = threadIdx.x;       // 1024 threads, 4 tokens each
    __shared__ int ssum[1024];

    int t0 = tid * 4;
    int flag[4]; float wv[4];
    int cnt = 0;
#pragma unroll
    for (int j = 0; j < 4; j++) {
        int t = t0 + j;
        int s0 = g_sel[t * 2], s1 = g_sel[t * 2 + 1];
        flag[j] = 0; wv[j] = 0.f;
        if (s0 == e)      { flag[j] = 1; wv[j] = g_w[t * 2]; }
        else if (s1 == e) { flag[j] = 1; wv[j] = g_w[t * 2 + 1]; }
        cnt += flag[j];
    }
    ssum[tid] = cnt;
    __syncthreads();
    for (int off = 1; off < 1024; off <<= 1) {
        int v = (tid >= off) ? ssum[tid - off] : 0;
        __syncthreads();
        ssum[tid] += v;
        __syncthreads();
    }
    int pos = ssum[tid] - cnt;   // exclusive prefix
#pragma unroll
    for (int j = 0; j < 4; j++) {
        if (flag[j]) {
            g_list[e * N_TOK + pos] = t0 + j;
            g_lw[e * N_TOK + pos] = wv[j];
            pos++;
        }
    }
    if (tid == 1023) g_count[e] = ssum[1023];
}

// ---------------- GEMM1: h = relu(gather(x) @ W1[e] + b1[e]) ----------------
__global__ void __launch_bounds__(256, 2) ffn1_kernel(
    const float* __restrict__ x, const float* __restrict__ W1, const float* __restrict__ b1) {
    int e = blockIdx.z;
    int cnt = g_count[e];
    int rowTile = blockIdx.y * BM;
    if (rowTile >= cnt) return;
    int colTile = blockIdx.x * BN;
    const float* B = W1 + (size_t)e * D_DIM * H_DIM;

    __shared__ float As[BK][BM];
    __shared__ float Bs[BK][BN];
    __shared__ int toks[BM];

    int tid = threadIdx.x;
    if (tid < BM) {
        int r = rowTile + tid;
        toks[tid] = (r < cnt) ? g_list[e * N_TOK + r] : -1;
    }
    __syncthreads();

    int tx = tid & 15, ty = tid >> 4;
    int aRow = tid >> 1;
    int aK = (tid & 1) * 4;
    int bRow = tid >> 5;
    int bCol = (tid & 31) * 4;

    int tokA = toks[aRow];
    const float* aPtr = (tokA >= 0) ? (x + (size_t)tokA * D_DIM) : nullptr;

    float acc[8][8];
#pragma unroll
    for (int i = 0; i < 8; i++)
#pragma unroll
        for (int j = 0; j < 8; j++) acc[i][j] = 0.f;

    for (int k0 = 0; k0 < D_DIM; k0 += BK) {
        float4 av = aPtr ? *(const float4*)(aPtr + k0 + aK) : make_float4(0.f, 0.f, 0.f, 0.f);
        float4 bv = *(const float4*)(B + (size_t)(k0 + bRow) * H_DIM + colTile + bCol);
        __syncthreads();
        As[aK + 0][aRow] = av.x; As[aK + 1][aRow] = av.y;
        As[aK + 2][aRow] = av.z; As[aK + 3][aRow] = av.w;
        *(float4*)&Bs[bRow][bCol] = bv;
        __syncthreads();
#pragma unroll
        for (int k = 0; k < BK; k++) {
            float4 a0 = *(float4*)&As[k][ty * 4];
            float4 a1 = *(float4*)&As[k][64 + ty * 4];
            float4 b0 = *(float4*)&Bs[k][tx * 4];
            float4 b1v = *(float4*)&Bs[k][64 + tx * 4];
            float ra[8] = {a0.x, a0.y, a0.z, a0.w, a1.x, a1.y, a1.z, a1.w};
            float rb[8] = {b0.x, b0.y, b0.z, b0.w, b1v.x, b1v.y, b1v.z, b1v.w};
#pragma unroll
            for (int i = 0; i < 8; i++)
#pragma unroll
                for (int j = 0; j < 8; j++) acc[i][j] += ra[i] * rb[j];
        }
    }

    // epilogue: bias + relu -> g_h
#pragma unroll
    for (int ih = 0; ih < 2; ih++) {
#pragma unroll
        for (int i = 0; i < 4; i++) {
            int r = rowTile + ih * 64 + ty * 4 + i;
            if (r >= cnt) continue;
            size_t base = ((size_t)(e * N_TOK + r)) * H_DIM + colTile;
#pragma unroll
            for (int jh = 0; jh < 2; jh++) {
                int c = jh * 64 + tx * 4;
                float4 bias = *(const float4*)(b1 + (size_t)e * H_DIM + colTile + c);
                float4 o;
                o.x = fmaxf(acc[ih * 4 + i][jh * 4 + 0] + bias.x, 0.f);
                o.y = fmaxf(acc[ih * 4 + i][jh * 4 + 1] + bias.y, 0.f);
                o.z = fmaxf(acc[ih * 4 + i][jh * 4 + 2] + bias.z, 0.f);
                o.w = fmaxf(acc[ih * 4 + i][jh * 4 + 3] + bias.w, 0.f);
                *(float4*)(g_h + base + c) = o;
            }
        }
    }
}

// ---------------- GEMM2: out += w * relu(h @ W2[e] + b2[e]) ----------------
__global__ void __launch_bounds__(256, 2) ffn2_kernel(
    const float* __restrict__ W2, const float* __restrict__ b2, float* __restrict__ out) {
    int e = blockIdx.z;
    int cnt = g_count[e];
    int rowTile = blockIdx.y * BM;
    if (rowTile >= cnt) return;
    int colTile = blockIdx.x * BN;
    const float* B = W2 + (size_t)e * H_DIM * O_DIM;

    __shared__ float As[BK][BM];
    __shared__ float Bs[BK][BN];
    __shared__ int toks[BM];
    __shared__ float wls[BM];

    int tid = threadIdx.x;
    if (tid < BM) {
        int r = rowTile + tid;
        bool v = (r < cnt);
        toks[tid] = v ? g_list[e * N_TOK + r] : -1;
        wls[tid]  = v ? g_lw[e * N_TOK + r] : 0.f;
    }
    __syncthreads();

    int tx = tid & 15, ty = tid >> 4;
    int aRow = tid >> 1;
    int aK = (tid & 1) * 4;
    int bRow = tid >> 5;
    int bCol = (tid & 31) * 4;

    bool aValid = (rowTile + aRow) < cnt;
    const float* aPtr = g_h + ((size_t)(e * N_TOK + rowTile + aRow)) * H_DIM;

    float acc[8][8];
#pragma unroll
    for (int i = 0; i < 8; i++)
#pragma unroll
        for (int j = 0; j < 8; j++) acc[i][j] = 0.f;

    for (int k0 = 0; k0 < H_DIM; k0 += BK) {
        float4 av = aValid ? *(const float4*)(aPtr + k0 + aK) : make_float4(0.f, 0.f, 0.f, 0.f);
        float4 bv = *(const float4*)(B + (size_t)(k0 + bRow) * O_DIM + colTile + bCol);
        __syncthreads();
        As[aK + 0][aRow] = av.x; As[aK + 1][aRow] = av.y;
        As[aK + 2][aRow] = av.z; As[aK + 3][aRow] = av.w;
        *(float4*)&Bs[bRow][bCol] = bv;
        __syncthreads();
#pragma unroll
        for (int k = 0; k < BK; k++) {
            float4 a0 = *(float4*)&As[k][ty * 4];
            float4 a1 = *(float4*)&As[k][64 + ty * 4];
            float4 b0 = *(float4*)&Bs[k][tx * 4];
            float4 b1v = *(float4*)&Bs[k][64 + tx * 4];
            float ra[8] = {a0.x, a0.y, a0.z, a0.w, a1.x, a1.y, a1.z, a1.w};
            float rb[8] = {b0.x, b0.y, b0.z, b0.w, b1v.x, b1v.y, b1v.z, b1v.w};
#pragma unroll
            for (int i = 0; i < 8; i++)
#pragma unroll
                for (int j = 0; j < 8; j++) acc[i][j] += ra[i] * rb[j];
        }
    }

    // epilogue: bias + relu, scale by combine weight, accumulate into out
#pragma unroll
    for (int ih = 0; ih < 2; ih++) {
#pragma unroll
        for (int i = 0; i < 4; i++) {
            int rl = ih * 64 + ty * 4 + i;
            int r = rowTile + rl;
            if (r >= cnt) continue;
            int tok = toks[rl];
            float w = wls[rl];
            float* orow = out + (size_t)tok * O_DIM + colTile;
#pragma unroll
            for (int jh = 0; jh < 2; jh++) {
                int c = jh * 64 + tx * 4;
                float4 bias = *(const float4*)(b2 + (size_t)e * O_DIM + colTile + c);
                float y0 = fmaxf(acc[ih * 4 + i][jh * 4 + 0] + bias.x, 0.f) * w;
                float y1 = fmaxf(acc[ih * 4 + i][jh * 4 + 1] + bias.y, 0.f) * w;
                float y2 = fmaxf(acc[ih * 4 + i][jh * 4 + 2] + bias.z, 0.f) * w;
                float y3 = fmaxf(acc[ih * 4 + i][jh * 4 + 3] + bias.w, 0.f) * w;
                atomicAdd(orow + c + 0, y0);
                atomicAdd(orow + c + 1, y1);
                atomicAdd(orow + c + 2, y2);
                atomicAdd(orow + c + 3, y3);
            }
        }
    }
}

extern "C" void kernel_launch(void* const* d_in, const int* in_sizes, int n_in,
                              void* d_out, int out_size) {
    const float* x  = (const float*)d_in[0];
    const float* Wg = (const float*)d_in[1];
    const float* W1 = (const float*)d_in[2];
    const float* b1 = (const float*)d_in[3];
    const float* W2 = (const float*)d_in[4];
    const float* b2 = (const float*)d_in[5];
    float* out = (float*)d_out;

    cudaMemsetAsync(out, 0, (size_t)N_TOK * O_DIM * sizeof(float), 0);
    gate_kernel<<<N_TOK, 256>>>(x, Wg);
    build_lists_kernel<<<E_NUM, 1024>>>();
    ffn1_kernel<<<dim3(H_DIM / BN, N_TOK / BM, E_NUM), 256>>>(x, W1, b1);
    ffn2_kernel<<<dim3(O_DIM / BN, N_TOK / BM, E_NUM), 256>>>(W2, b2, out);
}

// round 5
// speedup vs baseline: 1.4595x; 1.4595x over previous
#include <cuda_runtime.h>
#include <cuda_bf16.h>
#include <stdint.h>
#include <math.h>

#define N_TOK 4096
#define D_DIM 1024
#define H_DIM 4096
#define O_DIM 1024
#define E_NUM 8

// ---------------- static device scratch (~400 MB total) ----------------
__device__ __nv_bfloat16 g_xhi[(size_t)N_TOK * D_DIM];
__device__ __nv_bfloat16 g_xlo[(size_t)N_TOK * D_DIM];
__device__ __nv_bfloat16 g_w1hi[(size_t)E_NUM * H_DIM * D_DIM];   // [e][h][d]
__device__ __nv_bfloat16 g_w1lo[(size_t)E_NUM * H_DIM * D_DIM];
__device__ __nv_bfloat16 g_w2hi[(size_t)E_NUM * O_DIM * H_DIM];   // [e][o][h]
__device__ __nv_bfloat16 g_w2lo[(size_t)E_NUM * O_DIM * H_DIM];
__device__ __nv_bfloat16 g_hhi[(size_t)2 * N_TOK * H_DIM];        // compact slots (sum counts = 2N)
__device__ __nv_bfloat16 g_hlo[(size_t)2 * N_TOK * H_DIM];
__device__ int   g_sel[N_TOK * 2];
__device__ float g_w[N_TOK * 2];
__device__ int   g_list[E_NUM * N_TOK];
__device__ float g_lw[E_NUM * N_TOK];
__device__ int   g_count[E_NUM];
__device__ int   g_base[E_NUM];

// ---------------- PTX helpers (sm_80-baseline only) ----------------
__device__ __forceinline__ uint32_t smem_u32(const void* p) {
    uint32_t a;
    asm("{ .reg .u64 t; cvta.to.shared.u64 t, %1; cvt.u32.u64 %0, t; }" : "=r"(a) : "l"(p));
    return a;
}

#define CPASYNC16(dst, src) \
    asm volatile("cp.async.cg.shared.global [%0], [%1], 16;" :: "r"(dst), "l"(src))
#define CP_COMMIT() asm volatile("cp.async.commit_group;" ::: "memory")
#define CP_WAIT1()  asm volatile("cp.async.wait_group 1;" ::: "memory")

#define LDSM4(r, a) \
    asm volatile("ldmatrix.sync.aligned.m8n8.x4.shared.b16 {%0,%1,%2,%3}, [%4];" \
                 : "=r"((r)[0]), "=r"((r)[1]), "=r"((r)[2]), "=r"((r)[3]) : "r"(a))

#define MMA16816(c, a, b0, b1) \
    asm volatile("mma.sync.aligned.m16n8k16.row.col.f32.bf16.bf16.f32 " \
                 "{%0,%1,%2,%3}, {%4,%5,%6,%7}, {%8,%9}, {%0,%1,%2,%3};" \
                 : "+f"((c)[0]), "+f"((c)[1]), "+f"((c)[2]), "+f"((c)[3]) \
                 : "r"((a)[0]), "r"((a)[1]), "r"((a)[2]), "r"((a)[3]), "r"(b0), "r"(b1))

// ---------------- smem layout ----------------
// toks[128] | wls[128] | bias[128] | 2 stages x { Ahi | Alo | Bhi | Blo }
// tile = 128 rows x 80 bytes (32 bf16 + 8 pad) = 10240 B; stage = 40960 B
#define SM_TOKS 0
#define SM_WLS  512
#define SM_BIAS 1024
#define SM_BUF  2048
#define TILE_B   10240
#define STAGE_B  40960
#define SMEM_BYTES (SM_BUF + 2 * STAGE_B)

// ---------------- gate ----------------
__global__ void gate_kernel(const float* __restrict__ x, const float* __restrict__ Wg) {
    int t = blockIdx.x;
    int tid = threadIdx.x;
    const float* xr = x + (size_t)t * D_DIM;
    float acc[E_NUM];
#pragma unroll
    for (int e = 0; e < E_NUM; e++) acc[e] = 0.f;
    for (int d = tid; d < D_DIM; d += 256) {
        float xv = xr[d];
        const float4 w0 = *(const float4*)(Wg + (size_t)d * E_NUM);
        const float4 w1 = *(const float4*)(Wg + (size_t)d * E_NUM + 4);
        acc[0] += xv * w0.x; acc[1] += xv * w0.y; acc[2] += xv * w0.z; acc[3] += xv * w0.w;
        acc[4] += xv * w1.x; acc[5] += xv * w1.y; acc[6] += xv * w1.z; acc[7] += xv * w1.w;
    }
    __shared__ float red[E_NUM][256];
#pragma unroll
    for (int e = 0; e < E_NUM; e++) red[e][tid] = acc[e];
    __syncthreads();
    for (int s = 128; s > 0; s >>= 1) {
        if (tid < s) {
#pragma unroll
            for (int e = 0; e < E_NUM; e++) red[e][tid] += red[e][tid + s];
        }
        __syncthreads();
    }
    if (tid == 0) {
        float v[E_NUM];
#pragma unroll
        for (int e = 0; e < E_NUM; e++) v[e] = fmaxf(red[e][0], 0.f);
        int i1 = 0; float m1 = v[0];
#pragma unroll
        for (int e = 1; e < E_NUM; e++) if (v[e] > m1) { m1 = v[e]; i1 = e; }
        int i2 = -1; float m2 = -1e30f;
#pragma unroll
        for (int e = 0; e < E_NUM; e++) if (e != i1 && v[e] > m2) { m2 = v[e]; i2 = e; }
        float eb = __expf(m2 - m1);
        float inv = 1.f / (1.f + eb);
        g_sel[t * 2 + 0] = i1;  g_w[t * 2 + 0] = inv;
        g_sel[t * 2 + 1] = i2;  g_w[t * 2 + 1] = eb * inv;
    }
}

// ---------------- per-expert token lists (deterministic scan) ----------------
__global__ void build_lists_kernel() {
    int e = blockIdx.x;
    int tid = threadIdx.x;  // 1024
    __shared__ int ssum[1024];
    int t0 = tid * 4;
    int flag[4]; float wv[4];
    int cnt = 0;
#pragma unroll
    for (int j = 0; j < 4; j++) {
        int t = t0 + j;
        int s0 = g_sel[t * 2], s1 = g_sel[t * 2 + 1];
        flag[j] = 0; wv[j] = 0.f;
        if (s0 == e)      { flag[j] = 1; wv[j] = g_w[t * 2]; }
        else if (s1 == e) { flag[j] = 1; wv[j] = g_w[t * 2 + 1]; }
        cnt += flag[j];
    }
    ssum[tid] = cnt;
    __syncthreads();
    for (int off = 1; off < 1024; off <<= 1) {
        int v = (tid >= off) ? ssum[tid - off] : 0;
        __syncthreads();
        ssum[tid] += v;
        __syncthreads();
    }
    int pos = ssum[tid] - cnt;
#pragma unroll
    for (int j = 0; j < 4; j++) {
        if (flag[j]) {
            g_list[e * N_TOK + pos] = t0 + j;
            g_lw[e * N_TOK + pos] = wv[j];
            pos++;
        }
    }
    if (tid == 1023) g_count[e] = ssum[1023];
}

// exclusive prefix over 8 counts -> slot bases (sum == 2*N_TOK)
__global__ void compute_base_kernel() {
    int b = 0;
#pragma unroll
    for (int e = 0; e < E_NUM; e++) { g_base[e] = b; b += g_count[e]; }
}

// ---------------- conversions ----------------
__device__ __forceinline__ void split_bf16(float v, __nv_bfloat16& h, __nv_bfloat16& l) {
    h = __float2bfloat16(v);
    l = __float2bfloat16(v - __bfloat162float(h));
}

__global__ void convert_x_kernel(const float* __restrict__ x) {
    size_t i = (size_t)blockIdx.x * 256 + threadIdx.x;
    float4 v = ((const float4*)x)[i];
    __nv_bfloat16 h0, h1, h2, h3, l0, l1, l2, l3;
    split_bf16(v.x, h0, l0); split_bf16(v.y, h1, l1);
    split_bf16(v.z, h2, l2); split_bf16(v.w, h3, l3);
    uint32_t ph0 = (uint32_t)__bfloat16_as_ushort(h0) | ((uint32_t)__bfloat16_as_ushort(h1) << 16);
    uint32_t ph1 = (uint32_t)__bfloat16_as_ushort(h2) | ((uint32_t)__bfloat16_as_ushort(h3) << 16);
    uint32_t pl0 = (uint32_t)__bfloat16_as_ushort(l0) | ((uint32_t)__bfloat16_as_ushort(l1) << 16);
    uint32_t pl1 = (uint32_t)__bfloat16_as_ushort(l2) | ((uint32_t)__bfloat16_as_ushort(l3) << 16);
    ((uint2*)g_xhi)[i] = make_uint2(ph0, ph1);
    ((uint2*)g_xlo)[i] = make_uint2(pl0, pl1);
}

// in: [e][R][C] fp32 -> out hi/lo: [e][C][R] bf16 (which: 0 = W1, 1 = W2)
__global__ void transpose_split_kernel(const float* __restrict__ in, int which, int R, int C) {
    int e = blockIdx.z;
    const float* src = in + (size_t)e * R * C;
    __nv_bfloat16* ohi = (which ? g_w2hi : g_w1hi) + (size_t)e * R * C;
    __nv_bfloat16* olo = (which ? g_w2lo : g_w1lo) + (size_t)e * R * C;
    __shared__ float t[32][33];
    int tx = threadIdx.x & 31, ty = threadIdx.x >> 5;
    int c0 = blockIdx.x * 32, r0 = blockIdx.y * 32;
#pragma unroll
    for (int j = 0; j < 4; j++)
        t[ty + 8 * j][tx] = src[(size_t)(r0 + ty + 8 * j) * C + c0 + tx];
    __syncthreads();
#pragma unroll
    for (int j = 0; j < 4; j++) {
        float v = t[tx][ty + 8 * j];
        int c = c0 + ty + 8 * j, r = r0 + tx;
        __nv_bfloat16 hb, lb; split_bf16(v, hb, lb);
        ohi[(size_t)c * R + r] = hb;
        olo[(size_t)c * R + r] = lb;
    }
}

// =============================================================================
// GEMM1: h[slot] = relu(x[tok] @ W1t[e]^T + b1[e])   (hi/lo bf16 out)
// CTA tile 128x128, BK=32, 8 warps (4x2), warp tile 32x64, mma.m16n8k16 bf16
// 3 split-products (AhBh + AhBl + AlBh) accumulated in fp32 regs.
// =============================================================================
__global__ void __launch_bounds__(256) ffn1_kernel(const float* __restrict__ b1) {
    int e = blockIdx.z;
    int cnt = g_count[e];
    int rowTile = blockIdx.y * 128;
    if (rowTile >= cnt) return;
    int sbase = g_base[e];
    int colTile = blockIdx.x * 128;

    extern __shared__ char sm[];
    uint32_t sb = smem_u32(sm);
    int tid = threadIdx.x;
    int*   toksS = (int*)(sm + SM_TOKS);
    float* biasS = (float*)(sm + SM_BIAS);

    if (tid < 128) {
        int r = rowTile + tid;
        toksS[tid] = (r < cnt) ? g_list[e * N_TOK + r] : 0;
        biasS[tid] = b1[(size_t)e * H_DIM + colTile + tid];
    }
    __syncthreads();

    const int NIT = D_DIM / 32;  // 32

    auto load_stage = [&](int p, int it) {
        int k0 = it * 32;
        uint32_t base = sb + SM_BUF + p * STAGE_B;
#pragma unroll
        for (int j = 0; j < 8; j++) {
            int idx = j * 256 + tid;
            int tile = idx >> 9, v = idx & 511, row = v >> 2, ch = v & 3;
            uint32_t dst = base + tile * TILE_B + row * 80 + ch * 16;
            const __nv_bfloat16* src;
            if (tile == 0)      src = g_xhi + (size_t)toksS[row] * D_DIM + k0 + ch * 8;
            else if (tile == 1) src = g_xlo + (size_t)toksS[row] * D_DIM + k0 + ch * 8;
            else if (tile == 2) src = g_w1hi + (size_t)(e * H_DIM + colTile + row) * D_DIM + k0 + ch * 8;
            else                src = g_w1lo + (size_t)(e * H_DIM + colTile + row) * D_DIM + k0 + ch * 8;
            CPASYNC16(dst, src);
        }
    };

    int lane = tid & 31, w = tid >> 5;
    int wm = w & 3, wn = w >> 2;
    uint32_t aOff[2];
#pragma unroll
    for (int mi = 0; mi < 2; mi++)
        aOff[mi] = (uint32_t)(wm * 32 + mi * 16 + (lane & 15)) * 80 + (lane >> 4) * 16;
    uint32_t bOff[4];
#pragma unroll
    for (int np = 0; np < 4; np++) {
        int n = wn * 64 + np * 16 + (lane & 7) + ((lane >= 16) ? 8 : 0);
        bOff[np] = (uint32_t)n * 80 + ((lane & 8) ? 16 : 0);
    }

    float c[64];
#pragma unroll
    for (int i = 0; i < 64; i++) c[i] = 0.f;

    load_stage(0, 0); CP_COMMIT();
    load_stage(1, 1); CP_COMMIT();

    for (int it = 0; it < NIT; it++) {
        int p = it & 1;
        CP_WAIT1();
        __syncthreads();
        uint32_t base = sb + SM_BUF + p * STAGE_B;
#pragma unroll
        for (int ks = 0; ks < 2; ks++) {
            uint32_t ah[8], al[8], bh[16], bl[16];
            LDSM4(ah + 0, base + aOff[0] + ks * 32);
            LDSM4(ah + 4, base + aOff[1] + ks * 32);
            LDSM4(al + 0, base + TILE_B + aOff[0] + ks * 32);
            LDSM4(al + 4, base + TILE_B + aOff[1] + ks * 32);
#pragma unroll
            for (int np = 0; np < 4; np++) {
                LDSM4(bh + np * 4, base + 2 * TILE_B + bOff[np] + ks * 32);
                LDSM4(bl + np * 4, base + 3 * TILE_B + bOff[np] + ks * 32);
            }
#pragma unroll
            for (int mi = 0; mi < 2; mi++)
#pragma unroll
                for (int nb = 0; nb < 8; nb++) {
                    float* cc = c + (mi * 8 + nb) * 4;
                    int bi = (nb >> 1) * 4 + (nb & 1) * 2;
                    MMA16816(cc, ah + mi * 4, bh[bi], bh[bi + 1]);
                    MMA16816(cc, ah + mi * 4, bl[bi], bl[bi + 1]);
                    MMA16816(cc, al + mi * 4, bh[bi], bh[bi + 1]);
                }
        }
        __syncthreads();
        if (it + 2 < NIT) load_stage(p, it + 2);
        CP_COMMIT();
    }

    // ---- epilogue: bias + relu -> hi/lo bf16 (compact slot index) ----
    int g = lane >> 2, tq = lane & 3;
#pragma unroll
    for (int mi = 0; mi < 2; mi++)
#pragma unroll
        for (int half = 0; half < 2; half++) {
            int rloc = wm * 32 + mi * 16 + half * 8 + g;
            if (rowTile + rloc >= cnt) continue;
            size_t hb = ((size_t)(sbase + rowTile + rloc)) * H_DIM + colTile;
#pragma unroll
            for (int nb = 0; nb < 8; nb++) {
                int col = wn * 64 + nb * 8 + tq * 2;
                float v0 = fmaxf(c[(mi * 8 + nb) * 4 + half * 2 + 0] + biasS[col], 0.f);
                float v1 = fmaxf(c[(mi * 8 + nb) * 4 + half * 2 + 1] + biasS[col + 1], 0.f);
                __nv_bfloat16 h0, l0, h1, l1;
                split_bf16(v0, h0, l0); split_bf16(v1, h1, l1);
                *(uint32_t*)(g_hhi + hb + col) =
                    (uint32_t)__bfloat16_as_ushort(h0) | ((uint32_t)__bfloat16_as_ushort(h1) << 16);
                *(uint32_t*)(g_hlo + hb + col) =
                    (uint32_t)__bfloat16_as_ushort(l0) | ((uint32_t)__bfloat16_as_ushort(l1) << 16);
            }
        }
}

// =============================================================================
// GEMM2: out[tok] += w * relu(h[slot] @ W2t[e]^T + b2[e])
// =============================================================================
__global__ void __launch_bounds__(256) ffn2_kernel(const float* __restrict__ b2,
                                                   float* __restrict__ out) {
    int e = blockIdx.z;
    int cnt = g_count[e];
    int rowTile = blockIdx.y * 128;
    if (rowTile >= cnt) return;
    int sbase = g_base[e];
    int colTile = blockIdx.x * 128;

    extern __shared__ char sm[];
    uint32_t sb = smem_u32(sm);
    int tid = threadIdx.x;
    int*   toksS = (int*)(sm + SM_TOKS);
    float* wlsS  = (float*)(sm + SM_WLS);
    float* biasS = (float*)(sm + SM_BIAS);

    if (tid < 128) {
        int r = rowTile + tid;
        bool v = (r < cnt);
        toksS[tid] = v ? g_list[e * N_TOK + r] : 0;
        wlsS[tid]  = v ? g_lw[e * N_TOK + r] : 0.f;
        biasS[tid] = b2[(size_t)e * O_DIM + colTile + tid];
    }
    __syncthreads();

    const int NIT = H_DIM / 32;  // 128

    auto load_stage = [&](int p, int it) {
        int k0 = it * 32;
        uint32_t base = sb + SM_BUF + p * STAGE_B;
#pragma unroll
        for (int j = 0; j < 8; j++) {
            int idx = j * 256 + tid;
            int tile = idx >> 9, v = idx & 511, row = v >> 2, ch = v & 3;
            uint32_t dst = base + tile * TILE_B + row * 80 + ch * 16;
            const __nv_bfloat16* src;
            int arow = sbase + rowTile + row;
            if (arow >= sbase + cnt) arow = sbase;   // clamp (weight 0 in epilogue)
            if (tile == 0)      src = g_hhi + (size_t)arow * H_DIM + k0 + ch * 8;
            else if (tile == 1) src = g_hlo + (size_t)arow * H_DIM + k0 + ch * 8;
            else if (tile == 2) src = g_w2hi + (size_t)(e * O_DIM + colTile + row) * H_DIM + k0 + ch * 8;
            else                src = g_w2lo + (size_t)(e * O_DIM + colTile + row) * H_DIM + k0 + ch * 8;
            CPASYNC16(dst, src);
        }
    };

    int lane = tid & 31, w = tid >> 5;
    int wm = w & 3, wn = w >> 2;
    uint32_t aOff[2];
#pragma unroll
    for (int mi = 0; mi < 2; mi++)
        aOff[mi] = (uint32_t)(wm * 32 + mi * 16 + (lane & 15)) * 80 + (lane >> 4) * 16;
    uint32_t bOff[4];
#pragma unroll
    for (int np = 0; np < 4; np++) {
        int n = wn * 64 + np * 16 + (lane & 7) + ((lane >= 16) ? 8 : 0);
        bOff[np] = (uint32_t)n * 80 + ((lane & 8) ? 16 : 0);
    }

    float c[64];
#pragma unroll
    for (int i = 0; i < 64; i++) c[i] = 0.f;

    load_stage(0, 0); CP_COMMIT();
    load_stage(1, 1); CP_COMMIT();

    for (int it = 0; it < NIT; it++) {
        int p = it & 1;
        CP_WAIT1();
        __syncthreads();
        uint32_t base = sb + SM_BUF + p * STAGE_B;
#pragma unroll
        for (int ks = 0; ks < 2; ks++) {
            uint32_t ah[8], al[8], bh[16], bl[16];
            LDSM4(ah + 0, base + aOff[0] + ks * 32);
            LDSM4(ah + 4, base + aOff[1] + ks * 32);
            LDSM4(al + 0, base + TILE_B + aOff[0] + ks * 32);
            LDSM4(al + 4, base + TILE_B + aOff[1] + ks * 32);
#pragma unroll
            for (int np = 0; np < 4; np++) {
                LDSM4(bh + np * 4, base + 2 * TILE_B + bOff[np] + ks * 32);
                LDSM4(bl + np * 4, base + 3 * TILE_B + bOff[np] + ks * 32);
            }
#pragma unroll
            for (int mi = 0; mi < 2; mi++)
#pragma unroll
                for (int nb = 0; nb < 8; nb++) {
                    float* cc = c + (mi * 8 + nb) * 4;
                    int bi = (nb >> 1) * 4 + (nb & 1) * 2;
                    MMA16816(cc, ah + mi * 4, bh[bi], bh[bi + 1]);
                    MMA16816(cc, ah + mi * 4, bl[bi], bl[bi + 1]);
                    MMA16816(cc, al + mi * 4, bh[bi], bh[bi + 1]);
                }
        }
        __syncthreads();
        if (it + 2 < NIT) load_stage(p, it + 2);
        CP_COMMIT();
    }

    // ---- epilogue: bias + relu, scale by combine weight, atomic accumulate ----
    int g = lane >> 2, tq = lane & 3;
#pragma unroll
    for (int mi = 0; mi < 2; mi++)
#pragma unroll
        for (int half = 0; half < 2; half++) {
            int rloc = wm * 32 + mi * 16 + half * 8 + g;
            if (rowTile + rloc >= cnt) continue;
            int tok = toksS[rloc];
            float wc = wlsS[rloc];
            float* orow = out + (size_t)tok * O_DIM + colTile;
#pragma unroll
            for (int nb = 0; nb < 8; nb++) {
                int col = wn * 64 + nb * 8 + tq * 2;
                float v0 = fmaxf(c[(mi * 8 + nb) * 4 + half * 2 + 0] + biasS[col], 0.f) * wc;
                float v1 = fmaxf(c[(mi * 8 + nb) * 4 + half * 2 + 1] + biasS[col + 1], 0.f) * wc;
                atomicAdd(orow + col, v0);
                atomicAdd(orow + col + 1, v1);
            }
        }
}

// ---------------- host ----------------
extern "C" void kernel_launch(void* const* d_in, const int* in_sizes, int n_in,
                              void* d_out, int out_size) {
    const float* x  = (const float*)d_in[0];
    const float* Wg = (const float*)d_in[1];
    const float* W1 = (const float*)d_in[2];
    const float* b1 = (const float*)d_in[3];
    const float* W2 = (const float*)d_in[4];
    const float* b2 = (const float*)d_in[5];
    float* out = (float*)d_out;

    cudaFuncSetAttribute(ffn1_kernel, cudaFuncAttributeMaxDynamicSharedMemorySize, SMEM_BYTES);
    cudaFuncSetAttribute(ffn2_kernel, cudaFuncAttributeMaxDynamicSharedMemorySize, SMEM_BYTES);

    cudaMemsetAsync(out, 0, (size_t)N_TOK * O_DIM * sizeof(float), 0);
    convert_x_kernel<<<(N_TOK * D_DIM / 4) / 256, 256>>>(x);
    transpose_split_kernel<<<dim3(H_DIM / 32, D_DIM / 32, E_NUM), 256>>>(W1, 0, D_DIM, H_DIM);
    transpose_split_kernel<<<dim3(O_DIM / 32, H_DIM / 32, E_NUM), 256>>>(W2, 1, H_DIM, O_DIM);
    gate_kernel<<<N_TOK, 256>>>(x, Wg);
    build_lists_kernel<<<E_NUM, 1024>>>();
    compute_base_kernel<<<1, 1>>>();
    ffn1_kernel<<<dim3(H_DIM / 128, N_TOK / 128, E_NUM), 256, SMEM_BYTES>>>(b1);
    ffn2_kernel<<<dim3(O_DIM / 128, N_TOK / 128, E_NUM), 256, SMEM_BYTES>>>(b2, out);
}

// round 7
// speedup vs baseline: 2.2246x; 1.5243x over previous
#include <cuda_runtime.h>
#include <cuda_bf16.h>
#include <stdint.h>
#include <math.h>

#define N_TOK 4096
#define D_DIM 1024
#define H_DIM 4096
#define O_DIM 1024
#define E_NUM 8

// ---------------- static device scratch (~400 MB total) ----------------
__device__ __nv_bfloat16 g_xhi[(size_t)N_TOK * D_DIM];
__device__ __nv_bfloat16 g_xlo[(size_t)N_TOK * D_DIM];
__device__ __nv_bfloat16 g_w1hi[(size_t)E_NUM * H_DIM * D_DIM];   // [e][h][d] (transposed)
__device__ __nv_bfloat16 g_w1lo[(size_t)E_NUM * H_DIM * D_DIM];
__device__ __nv_bfloat16 g_w2hi[(size_t)E_NUM * O_DIM * H_DIM];   // [e][o][h] (transposed)
__device__ __nv_bfloat16 g_w2lo[(size_t)E_NUM * O_DIM * H_DIM];
__device__ __nv_bfloat16 g_hhi[(size_t)2 * N_TOK * H_DIM];        // compact slots
__device__ __nv_bfloat16 g_hlo[(size_t)2 * N_TOK * H_DIM];
__device__ int   g_sel[N_TOK * 2];
__device__ float g_w[N_TOK * 2];
__device__ int   g_list[E_NUM * N_TOK];
__device__ float g_lw[E_NUM * N_TOK];
__device__ int   g_count[E_NUM];

// ---------------- PTX helpers (sm_80-baseline only) ----------------
__device__ __forceinline__ uint32_t smem_u32(const void* p) {
    uint32_t a;
    asm("{ .reg .u64 t; cvta.to.shared.u64 t, %1; cvt.u32.u64 %0, t; }" : "=r"(a) : "l"(p));
    return a;
}

#define CPASYNC16(dst, src) \
    asm volatile("cp.async.cg.shared.global [%0], [%1], 16;" :: "r"(dst), "l"(src))
#define CP_COMMIT() asm volatile("cp.async.commit_group;" ::: "memory")
#define CP_WAIT1()  asm volatile("cp.async.wait_group 1;" ::: "memory")

#define LDSM4(r, a) \
    asm volatile("ldmatrix.sync.aligned.m8n8.x4.shared.b16 {%0,%1,%2,%3}, [%4];" \
                 : "=r"((r)[0]), "=r"((r)[1]), "=r"((r)[2]), "=r"((r)[3]) : "r"(a))

#define MMA16816(c, a, b0, b1) \
    asm volatile("mma.sync.aligned.m16n8k16.row.col.f32.bf16.bf16.f32 " \
                 "{%0,%1,%2,%3}, {%4,%5,%6,%7}, {%8,%9}, {%0,%1,%2,%3};" \
                 : "+f"((c)[0]), "+f"((c)[1]), "+f"((c)[2]), "+f"((c)[3]) \
                 : "r"((a)[0]), "r"((a)[1]), "r"((a)[2]), "r"((a)[3]), "r"(b0), "r"(b1))

// ---------------- smem layout ----------------
// toks[128] | wls[128] | bias[128] | 2 stages x { Ahi | Alo | Bhi | Blo }
// tile = 128 rows x 80 bytes (32 bf16 + 8 pad) = 10240 B; stage = 40960 B
#define SM_TOKS 0
#define SM_WLS  512
#define SM_BIAS 1024
#define SM_BUF  2048
#define TILE_B   10240
#define STAGE_B  40960
#define SMEM_BYTES (SM_BUF + 2 * STAGE_B)

// ---------------- gate + x split (fused) ----------------
__global__ void gate_kernel(const float* __restrict__ x, const float* __restrict__ Wg) {
    int t = blockIdx.x;
    int tid = threadIdx.x;  // 256 threads, 4 cols each
    float4 v = ((const float4*)(x + (size_t)t * D_DIM))[tid];
    float vv[4] = {v.x, v.y, v.z, v.w};

    uint32_t ph[2], pl[2];
#pragma unroll
    for (int j = 0; j < 4; j++) {
        __nv_bfloat16 hb = __float2bfloat16(vv[j]);
        __nv_bfloat16 lb = __float2bfloat16(vv[j] - __bfloat162float(hb));
        uint32_t hbits = (uint32_t)__bfloat16_as_ushort(hb);
        uint32_t lbits = (uint32_t)__bfloat16_as_ushort(lb);
        if (j & 1) { ph[j >> 1] |= hbits << 16; pl[j >> 1] |= lbits << 16; }
        else       { ph[j >> 1]  = hbits;       pl[j >> 1]  = lbits; }
    }
    size_t xo = ((size_t)t * D_DIM + tid * 4) >> 2;
    ((uint2*)g_xhi)[xo] = make_uint2(ph[0], ph[1]);
    ((uint2*)g_xlo)[xo] = make_uint2(pl[0], pl[1]);

    float acc[E_NUM];
#pragma unroll
    for (int e = 0; e < E_NUM; e++) acc[e] = 0.f;
#pragma unroll
    for (int j = 0; j < 4; j++) {
        int d = tid * 4 + j;
        const float4 w0 = *(const float4*)(Wg + (size_t)d * E_NUM);
        const float4 w1 = *(const float4*)(Wg + (size_t)d * E_NUM + 4);
        acc[0] += vv[j] * w0.x; acc[1] += vv[j] * w0.y;
        acc[2] += vv[j] * w0.z; acc[3] += vv[j] * w0.w;
        acc[4] += vv[j] * w1.x; acc[5] += vv[j] * w1.y;
        acc[6] += vv[j] * w1.z; acc[7] += vv[j] * w1.w;
    }

    __shared__ float red[E_NUM][256];
#pragma unroll
    for (int e = 0; e < E_NUM; e++) red[e][tid] = acc[e];
    __syncthreads();
    for (int s = 128; s > 0; s >>= 1) {
        if (tid < s) {
#pragma unroll
            for (int e = 0; e < E_NUM; e++) red[e][tid] += red[e][tid + s];
        }
        __syncthreads();
    }
    if (tid == 0) {
        float v2[E_NUM];
#pragma unroll
        for (int e = 0; e < E_NUM; e++) v2[e] = fmaxf(red[e][0], 0.f);
        int i1 = 0; float m1 = v2[0];
#pragma unroll
        for (int e = 1; e < E_NUM; e++) if (v2[e] > m1) { m1 = v2[e]; i1 = e; }
        int i2 = -1; float m2 = -1e30f;
#pragma unroll
        for (int e = 0; e < E_NUM; e++) if (e != i1 && v2[e] > m2) { m2 = v2[e]; i2 = e; }
        float eb = __expf(m2 - m1);
        float inv = 1.f / (1.f + eb);
        g_sel[t * 2 + 0] = i1;  g_w[t * 2 + 0] = inv;
        g_sel[t * 2 + 1] = i2;  g_w[t * 2 + 1] = eb * inv;
    }
}

// ---------------- per-expert token lists (deterministic scan) ----------------
__global__ void build_lists_kernel() {
    int e = blockIdx.x;
    int tid = threadIdx.x;  // 1024
    __shared__ int ssum[1024];
    int t0 = tid * 4;
    int flag[4]; float wv[4];
    int cnt = 0;
#pragma unroll
    for (int j = 0; j < 4; j++) {
        int t = t0 + j;
        int s0 = g_sel[t * 2], s1 = g_sel[t * 2 + 1];
        flag[j] = 0; wv[j] = 0.f;
        if (s0 == e)      { flag[j] = 1; wv[j] = g_w[t * 2]; }
        else if (s1 == e) { flag[j] = 1; wv[j] = g_w[t * 2 + 1]; }
        cnt += flag[j];
    }
    ssum[tid] = cnt;
    __syncthreads();
    for (int off = 1; off < 1024; off <<= 1) {
        int v = (tid >= off) ? ssum[tid - off] : 0;
        __syncthreads();
        ssum[tid] += v;
        __syncthreads();
    }
    int pos = ssum[tid] - cnt;
#pragma unroll
    for (int j = 0; j < 4; j++) {
        if (flag[j]) {
            g_list[e * N_TOK + pos] = t0 + j;
            g_lw[e * N_TOK + pos] = wv[j];
            pos++;
        }
    }
    if (tid == 1023) g_count[e] = ssum[1023];
}

// ---------------- conversions ----------------
__device__ __forceinline__ void split_bf16(float v, __nv_bfloat16& h, __nv_bfloat16& l) {
    h = __float2bfloat16(v);
    l = __float2bfloat16(v - __bfloat162float(h));
}

__device__ __forceinline__ int slot_base(int e) {
    int b = 0;
#pragma unroll
    for (int i = 0; i < E_NUM; i++) if (i < e) b += g_count[i];
    return b;
}

// in: [e][R][C] fp32 -> out hi/lo: [e][C][R] bf16, packed uint2 stores
__global__ void transpose_split_kernel(const float* __restrict__ in, int which, int R, int C) {
    int e = blockIdx.z;
    const float* src = in + (size_t)e * R * C;
    __nv_bfloat16* ohi = (which ? g_w2hi : g_w1hi) + (size_t)e * R * C;
    __nv_bfloat16* olo = (which ? g_w2lo : g_w1lo) + (size_t)e * R * C;
    __shared__ float t[32][33];
    int tid = threadIdx.x;
    int tx = tid & 31, ty = tid >> 5;
    int c0 = blockIdx.x * 32, r0 = blockIdx.y * 32;
#pragma unroll
    for (int j = 0; j < 4; j++)
        t[ty + 8 * j][tx] = src[(size_t)(r0 + ty + 8 * j) * C + c0 + tx];
    __syncthreads();
    // store: thread -> out-row c = tid>>3, k-chunk g = tid&7 (4 consecutive r)
    int cc = tid >> 3, g = tid & 7;
    float v0 = t[g * 4 + 0][cc], v1 = t[g * 4 + 1][cc];
    float v2 = t[g * 4 + 2][cc], v3 = t[g * 4 + 3][cc];
    __nv_bfloat16 h0, l0, h1, l1, h2, l2, h3, l3;
    split_bf16(v0, h0, l0); split_bf16(v1, h1, l1);
    split_bf16(v2, h2, l2); split_bf16(v3, h3, l3);
    uint2 uh = make_uint2(
        (uint32_t)__bfloat16_as_ushort(h0) | ((uint32_t)__bfloat16_as_ushort(h1) << 16),
        (uint32_t)__bfloat16_as_ushort(h2) | ((uint32_t)__bfloat16_as_ushort(h3) << 16));
    uint2 ul = make_uint2(
        (uint32_t)__bfloat16_as_ushort(l0) | ((uint32_t)__bfloat16_as_ushort(l1) << 16),
        (uint32_t)__bfloat16_as_ushort(l2) | ((uint32_t)__bfloat16_as_ushort(l3) << 16));
    size_t ob = (size_t)(c0 + cc) * R + r0 + g * 4;
    *(uint2*)(ohi + ob) = uh;
    *(uint2*)(olo + ob) = ul;
}

// =============================================================================
// GEMM1: h[slot] = relu(x[tok] @ W1t[e]^T + b1[e])   (hi/lo bf16 out)
// CTA tile 128x128, BK=32, 8 warps (4x2), warp tile 32x64, mma.m16n8k16 bf16
// 3 split-products (AhBh + AhBl + AlBh) accumulated in fp32 regs.  [R5-proven]
// =============================================================================
__global__ void __launch_bounds__(256) ffn1_kernel(const float* __restrict__ b1) {
    int e = blockIdx.z;
    int cnt = g_count[e];
    int rowTile = blockIdx.y * 128;
    if (rowTile >= cnt) return;
    int sbase = slot_base(e);
    int colTile = blockIdx.x * 128;

    extern __shared__ char sm[];
    uint32_t sb = smem_u32(sm);
    int tid = threadIdx.x;
    int*   toksS = (int*)(sm + SM_TOKS);
    float* biasS = (float*)(sm + SM_BIAS);

    if (tid < 128) {
        int r = rowTile + tid;
        toksS[tid] = (r < cnt) ? g_list[e * N_TOK + r] : 0;
        biasS[tid] = b1[(size_t)e * H_DIM + colTile + tid];
    }
    __syncthreads();

    const int NIT = D_DIM / 32;  // 32

    auto load_stage = [&](int p, int it) {
        int k0 = it * 32;
        uint32_t base = sb + SM_BUF + p * STAGE_B;
#pragma unroll
        for (int j = 0; j < 8; j++) {
            int idx = j * 256 + tid;
            int tile = idx >> 9, v = idx & 511, row = v >> 2, ch = v & 3;
            uint32_t dst = base + tile * TILE_B + row * 80 + ch * 16;
            const __nv_bfloat16* src;
            if (tile == 0)      src = g_xhi + (size_t)toksS[row] * D_DIM + k0 + ch * 8;
            else if (tile == 1) src = g_xlo + (size_t)toksS[row] * D_DIM + k0 + ch * 8;
            else if (tile == 2) src = g_w1hi + (size_t)(e * H_DIM + colTile + row) * D_DIM + k0 + ch * 8;
            else                src = g_w1lo + (size_t)(e * H_DIM + colTile + row) * D_DIM + k0 + ch * 8;
            CPASYNC16(dst, src);
        }
    };

    int lane = tid & 31, w = tid >> 5;
    int wm = w & 3, wn = w >> 2;
    uint32_t aOff[2];
#pragma unroll
    for (int mi = 0; mi < 2; mi++)
        aOff[mi] = (uint32_t)(wm * 32 + mi * 16 + (lane & 15)) * 80 + (lane >> 4) * 16;
    uint32_t bOff[4];
#pragma unroll
    for (int np = 0; np < 4; np++) {
        int n = wn * 64 + np * 16 + (lane & 7) + ((lane >= 16) ? 8 : 0);
        bOff[np] = (uint32_t)n * 80 + ((lane & 8) ? 16 : 0);
    }

    float c[64];
#pragma unroll
    for (int i = 0; i < 64; i++) c[i] = 0.f;

    load_stage(0, 0); CP_COMMIT();
    load_stage(1, 1); CP_COMMIT();

    for (int it = 0; it < NIT; it++) {
        int p = it & 1;
        CP_WAIT1();
        __syncthreads();
        uint32_t base = sb + SM_BUF + p * STAGE_B;
#pragma unroll
        for (int ks = 0; ks < 2; ks++) {
            uint32_t ah[8], al[8], bh[16], bl[16];
            LDSM4(ah + 0, base + aOff[0] + ks * 32);
            LDSM4(ah + 4, base + aOff[1] + ks * 32);
            LDSM4(al + 0, base + TILE_B + aOff[0] + ks * 32);
            LDSM4(al + 4, base + TILE_B + aOff[1] + ks * 32);
#pragma unroll
            for (int np = 0; np < 4; np++) {
                LDSM4(bh + np * 4, base + 2 * TILE_B + bOff[np] + ks * 32);
                LDSM4(bl + np * 4, base + 3 * TILE_B + bOff[np] + ks * 32);
            }
#pragma unroll
            for (int mi = 0; mi < 2; mi++)
#pragma unroll
                for (int nb = 0; nb < 8; nb++) {
                    float* cc = c + (mi * 8 + nb) * 4;
                    int bi = (nb >> 1) * 4 + (nb & 1) * 2;
                    MMA16816(cc, ah + mi * 4, bh[bi], bh[bi + 1]);
                    MMA16816(cc, ah + mi * 4, bl[bi], bl[bi + 1]);
                    MMA16816(cc, al + mi * 4, bh[bi], bh[bi + 1]);
                }
        }
        __syncthreads();
        if (it + 2 < NIT) load_stage(p, it + 2);
        CP_COMMIT();
    }

    int g = lane >> 2, tq = lane & 3;
#pragma unroll
    for (int mi = 0; mi < 2; mi++)
#pragma unroll
        for (int half = 0; half < 2; half++) {
            int rloc = wm * 32 + mi * 16 + half * 8 + g;
            if (rowTile + rloc >= cnt) continue;
            size_t hb = ((size_t)(sbase + rowTile + rloc)) * H_DIM + colTile;
#pragma unroll
            for (int nb = 0; nb < 8; nb++) {
                int col = wn * 64 + nb * 8 + tq * 2;
                float v0 = fmaxf(c[(mi * 8 + nb) * 4 + half * 2 + 0] + biasS[col], 0.f);
                float v1 = fmaxf(c[(mi * 8 + nb) * 4 + half * 2 + 1] + biasS[col + 1], 0.f);
                __nv_bfloat16 h0, l0, h1, l1;
                split_bf16(v0, h0, l0); split_bf16(v1, h1, l1);
                *(uint32_t*)(g_hhi + hb + col) =
                    (uint32_t)__bfloat16_as_ushort(h0) | ((uint32_t)__bfloat16_as_ushort(h1) << 16);
                *(uint32_t*)(g_hlo + hb + col) =
                    (uint32_t)__bfloat16_as_ushort(l0) | ((uint32_t)__bfloat16_as_ushort(l1) << 16);
            }
        }
}

// =============================================================================
// GEMM2: out[tok] += w * relu(h[slot] @ W2t[e]^T + b2[e])   [R5-proven]
// =============================================================================
__global__ void __launch_bounds__(256) ffn2_kernel(const float* __restrict__ b2,
                                                   float* __restrict__ out) {
    int e = blockIdx.z;
    int cnt = g_count[e];
    int rowTile = blockIdx.y * 128;
    if (rowTile >= cnt) return;
    int sbase = slot_base(e);
    int colTile = blockIdx.x * 128;

    extern __shared__ char sm[];
    uint32_t sb = smem_u32(sm);
    int tid = threadIdx.x;
    int*   toksS = (int*)(sm + SM_TOKS);
    float* wlsS  = (float*)(sm + SM_WLS);
    float* biasS = (float*)(sm + SM_BIAS);

    if (tid < 128) {
        int r = rowTile + tid;
        bool v = (r < cnt);
        toksS[tid] = v ? g_list[e * N_TOK + r] : 0;
        wlsS[tid]  = v ? g_lw[e * N_TOK + r] : 0.f;
        biasS[tid] = b2[(size_t)e * O_DIM + colTile + tid];
    }
    __syncthreads();

    const int NIT = H_DIM / 32;  // 128

    auto load_stage = [&](int p, int it) {
        int k0 = it * 32;
        uint32_t base = sb + SM_BUF + p * STAGE_B;
#pragma unroll
        for (int j = 0; j < 8; j++) {
            int idx = j * 256 + tid;
            int tile = idx >> 9, v = idx & 511, row = v >> 2, ch = v & 3;
            uint32_t dst = base + tile * TILE_B + row * 80 + ch * 16;
            const __nv_bfloat16* src;
            int arow = sbase + rowTile + row;
            if (arow >= sbase + cnt) arow = sbase;   // clamp (weight 0 in epilogue)
            if (tile == 0)      src = g_hhi + (size_t)arow * H_DIM + k0 + ch * 8;
            else if (tile == 1) src = g_hlo + (size_t)arow * H_DIM + k0 + ch * 8;
            else if (tile == 2) src = g_w2hi + (size_t)(e * O_DIM + colTile + row) * H_DIM + k0 + ch * 8;
            else                src = g_w2lo + (size_t)(e * O_DIM + colTile + row) * H_DIM + k0 + ch * 8;
            CPASYNC16(dst, src);
        }
    };

    int lane = tid & 31, w = tid >> 5;
    int wm = w & 3, wn = w >> 2;
    uint32_t aOff[2];
#pragma unroll
    for (int mi = 0; mi < 2; mi++)
        aOff[mi] = (uint32_t)(wm * 32 + mi * 16 + (lane & 15)) * 80 + (lane >> 4) * 16;
    uint32_t bOff[4];
#pragma unroll
    for (int np = 0; np < 4; np++) {
        int n = wn * 64 + np * 16 + (lane & 7) + ((lane >= 16) ? 8 : 0);
        bOff[np] = (uint32_t)n * 80 + ((lane & 8) ? 16 : 0);
    }

    float c[64];
#pragma unroll
    for (int i = 0; i < 64; i++) c[i] = 0.f;

    load_stage(0, 0); CP_COMMIT();
    load_stage(1, 1); CP_COMMIT();

    for (int it = 0; it < NIT; it++) {
        int p = it & 1;
        CP_WAIT1();
        __syncthreads();
        uint32_t base = sb + SM_BUF + p * STAGE_B;
#pragma unroll
        for (int ks = 0; ks < 2; ks++) {
            uint32_t ah[8], al[8], bh[16], bl[16];
            LDSM4(ah + 0, base + aOff[0] + ks * 32);
            LDSM4(ah + 4, base + aOff[1] + ks * 32);
            LDSM4(al + 0, base + TILE_B + aOff[0] + ks * 32);
            LDSM4(al + 4, base + TILE_B + aOff[1] + ks * 32);
#pragma unroll
            for (int np = 0; np < 4; np++) {
                LDSM4(bh + np * 4, base + 2 * TILE_B + bOff[np] + ks * 32);
                LDSM4(bl + np * 4, base + 3 * TILE_B + bOff[np] + ks * 32);
            }
#pragma unroll
            for (int mi = 0; mi < 2; mi++)
#pragma unroll
                for (int nb = 0; nb < 8; nb++) {
                    float* cc = c + (mi * 8 + nb) * 4;
                    int bi = (nb >> 1) * 4 + (nb & 1) * 2;
                    MMA16816(cc, ah + mi * 4, bh[bi], bh[bi + 1]);
                    MMA16816(cc, ah + mi * 4, bl[bi], bl[bi + 1]);
                    MMA16816(cc, al + mi * 4, bh[bi], bh[bi + 1]);
                }
        }
        __syncthreads();
        if (it + 2 < NIT) load_stage(p, it + 2);
        CP_COMMIT();
    }

    int g = lane >> 2, tq = lane & 3;
#pragma unroll
    for (int mi = 0; mi < 2; mi++)
#pragma unroll
        for (int half = 0; half < 2; half++) {
            int rloc = wm * 32 + mi * 16 + half * 8 + g;
            if (rowTile + rloc >= cnt) continue;
            int tok = toksS[rloc];
            float wc = wlsS[rloc];
            float* orow = out + (size_t)tok * O_DIM + colTile;
#pragma unroll
            for (int nb = 0; nb < 8; nb++) {
                int col = wn * 64 + nb * 8 + tq * 2;
                float v0 = fmaxf(c[(mi * 8 + nb) * 4 + half * 2 + 0] + biasS[col], 0.f) * wc;
                float v1 = fmaxf(c[(mi * 8 + nb) * 4 + half * 2 + 1] + biasS[col + 1], 0.f) * wc;
                atomicAdd(orow + col, v0);
                atomicAdd(orow + col + 1, v1);
            }
        }
}

// ---------------- host ----------------
extern "C" void kernel_launch(void* const* d_in, const int* in_sizes, int n_in,
                              void* d_out, int out_size) {
    const float* x  = (const float*)d_in[0];
    const float* Wg = (const float*)d_in[1];
    const float* W1 = (const float*)d_in[2];
    const float* b1 = (const float*)d_in[3];
    const float* W2 = (const float*)d_in[4];
    const float* b2 = (const float*)d_in[5];
    float* out = (float*)d_out;

    cudaFuncSetAttribute(ffn1_kernel, cudaFuncAttributeMaxDynamicSharedMemorySize, SMEM_BYTES);
    cudaFuncSetAttribute(ffn2_kernel, cudaFuncAttributeMaxDynamicSharedMemorySize, SMEM_BYTES);

    // Launch order chosen so the profiler's capture slot (5th launch) = ffn1.
    transpose_split_kernel<<<dim3(H_DIM / 32, D_DIM / 32, E_NUM), 256>>>(W1, 0, D_DIM, H_DIM);
    transpose_split_kernel<<<dim3(O_DIM / 32, H_DIM / 32, E_NUM), 256>>>(W2, 1, H_DIM, O_DIM);
    gate_kernel<<<N_TOK, 256>>>(x, Wg);
    build_lists_kernel<<<E_NUM, 1024>>>();
    ffn1_kernel<<<dim3(H_DIM / 128, N_TOK / 128, E_NUM), 256, SMEM_BYTES>>>(b1);
    cudaMemsetAsync(out, 0, (size_t)N_TOK * O_DIM * sizeof(float), 0);
    ffn2_kernel<<<dim3(O_DIM / 128, N_TOK / 128, E_NUM), 256, SMEM_BYTES>>>(b2, out);
}